// round 13
// baseline (speedup 1.0000x reference)
#include <cuda_runtime.h>
#include <math.h>
#include <stdint.h>

#define DEPTH   6
#define D_MODEL 512
#define N_HEADS 8
#define D_HEAD  64
#define D_FF    2048
#define SEQ_T   2048
#define VOCAB   256
#define BB      2
#define MROWS   (BB * SEQ_T)     /* 4096 */
#define EPS_LN  1e-5f
#define NQT     (SEQ_T / 64)     /* 32 q-tiles */

// ---------------------------------------------------------------------------
// Static device scratch
// ---------------------------------------------------------------------------
__device__ float g_h   [MROWS * D_MODEL];
__device__ float g_ln  [MROWS * D_MODEL];
__device__ float g_qkv [MROWS * 3 * D_MODEL];
__device__ float g_attn[MROWS * D_MODEL];
__device__ float g_ff  [MROWS * D_FF];
// tf32-pre-rounded weight copies
__device__ float g_wqkv [DEPTH * 3 * D_MODEL * D_MODEL];
__device__ float g_wproj[DEPTH * D_MODEL * D_MODEL];
__device__ float g_wfc1 [DEPTH * D_FF * D_MODEL];
__device__ float g_wfc2 [DEPTH * D_MODEL * D_FF];
__device__ float g_whead[VOCAB * D_MODEL];

// ---------------------------------------------------------------------------
// Helpers
// ---------------------------------------------------------------------------
__device__ __forceinline__ unsigned f2tf(float f) {
    unsigned u;
    asm("cvt.rna.tf32.f32 %0, %1;" : "=r"(u) : "f"(f));
    return u;
}

__device__ __forceinline__ float roundtf(float f) {
    return __uint_as_float(f2tf(f));
}

__device__ __forceinline__ uint32_t smem_u32(const void* p) {
    uint32_t a;
    asm("{ .reg .u64 t; cvta.to.shared.u64 t, %1; cvt.u32.u64 %0, t; }"
        : "=r"(a) : "l"(p));
    return a;
}

__device__ __forceinline__ float gelu_exact(float x) {
    return 0.5f * x * (1.0f + erff(x * 0.70710678118654752f));
}

// ---------------------------------------------------------------------------
// Elementwise tf32 rounding (weight pre-pass)
// ---------------------------------------------------------------------------
__global__ void round_tf32_kernel(const float* __restrict__ in,
                                  float* __restrict__ out, int n) {
    int i = blockIdx.x * blockDim.x + threadIdx.x;
    if (i < n) out[i] = roundtf(in[i]);
}

// ---------------------------------------------------------------------------
// Embedding
// ---------------------------------------------------------------------------
__global__ void embed_kernel(const int* __restrict__ x,
                             const float* __restrict__ tok,
                             const float* __restrict__ pos,
                             float* __restrict__ h) {
    int i = blockIdx.x * blockDim.x + threadIdx.x;
    if (i >= MROWS * D_MODEL) return;
    int d   = i & (D_MODEL - 1);
    int row = i >> 9;
    int t   = row & (SEQ_T - 1);
    int tok_id = x[row];
    h[i] = tok[tok_id * D_MODEL + d] + pos[t * D_MODEL + d];
}

// ---------------------------------------------------------------------------
// LayerNorm (outputs tf32-rounded: all consumers are GEMM X operands)
// ---------------------------------------------------------------------------
__global__ void ln_kernel(const float* __restrict__ in,
                          const float* __restrict__ w,
                          const float* __restrict__ b,
                          float* __restrict__ out) {
    int row = blockIdx.x;
    int tid = threadIdx.x;
    const float* xr = in + (size_t)row * D_MODEL;

    float v0 = xr[tid];
    float v1 = xr[tid + 256];

    __shared__ float red[256];
    red[tid] = v0 + v1;
    __syncthreads();
    #pragma unroll
    for (int s = 128; s > 0; s >>= 1) {
        if (tid < s) red[tid] += red[tid + s];
        __syncthreads();
    }
    float mu = red[0] * (1.0f / D_MODEL);
    __syncthreads();

    float d0 = v0 - mu, d1 = v1 - mu;
    red[tid] = d0 * d0 + d1 * d1;
    __syncthreads();
    #pragma unroll
    for (int s = 128; s > 0; s >>= 1) {
        if (tid < s) red[tid] += red[tid + s];
        __syncthreads();
    }
    float rstd = rsqrtf(red[0] * (1.0f / D_MODEL) + EPS_LN);

    float* orow = out + (size_t)row * D_MODEL;
    orow[tid]       = roundtf(d0 * rstd * w[tid]       + b[tid]);
    orow[tid + 256] = roundtf(d1 * rstd * w[tid + 256] + b[tid + 256]);
}

// ---------------------------------------------------------------------------
// tf32 mma.sync GEMM v3: cp.async 2-stage pipeline, pre-rounded inputs.
// Y[M,N] = X[M,K] @ W[N,K]^T. 128x128 tile, BK=32, 256 threads.
// smem layout per stage: X [128][36] fp32-as-tf32 bits, W [128][36].
// EPI: 0 store, 1 Y+=, 2 gelu(rounded).
// ---------------------------------------------------------------------------
#define S36     36
#define TILE_U  (128 * S36)                 /* 4608 words */
#define GEMM_SMEM (2 * 2 * TILE_U * 4)      /* 73728 B */

__device__ __forceinline__ void gemm_issue(const float* X, const float* W,
                                           uint32_t xs, uint32_t ws,
                                           int rowBase, int colBase, int K,
                                           int koff, int tid) {
    #pragma unroll
    for (int c = 0; c < 4; c++) {
        int id = c * 256 + tid;
        int row = id >> 3;
        int kc = (id & 7) * 4;
        const float* sx = X + (size_t)(rowBase + row) * K + koff + kc;
        const float* sw = W + (size_t)(colBase + row) * K + koff + kc;
        uint32_t dx = xs + (uint32_t)(row * S36 + kc) * 4;
        uint32_t dw = ws + (uint32_t)(row * S36 + kc) * 4;
        asm volatile("cp.async.cg.shared.global [%0], [%1], 16;"
                     :: "r"(dx), "l"(sx) : "memory");
        asm volatile("cp.async.cg.shared.global [%0], [%1], 16;"
                     :: "r"(dw), "l"(sw) : "memory");
    }
}

template <int EPI>
__global__ __launch_bounds__(256, 2)
void gemm_tf32_kernel(const float* __restrict__ X,
                      const float* __restrict__ W,
                      float* __restrict__ Y,
                      int M, int N, int K) {
    extern __shared__ float smf[];
    uint32_t sb = smem_u32(smf);

    int tid = threadIdx.x;
    int w = tid >> 5, l = tid & 31;
    int wm = w & 3;
    int wn = w >> 2;
    int g = l >> 2, t = l & 3;
    int rowBase = blockIdx.y * 128;
    int colBase = blockIdx.x * 128;

    float acc[2][8][4];
    #pragma unroll
    for (int i = 0; i < 2; i++)
        #pragma unroll
        for (int j = 0; j < 8; j++)
            #pragma unroll
            for (int c = 0; c < 4; c++) acc[i][j][c] = 0.0f;

    int nCh = K >> 5;

    // prologue: stage 0 = chunk 0
    gemm_issue(X, W, sb, sb + TILE_U * 4, rowBase, colBase, K, 0, tid);
    asm volatile("cp.async.commit_group;" ::: "memory");

    for (int ch = 0; ch < nCh; ch++) {
        int nxt = ch + 1;
        if (nxt < nCh) {
            uint32_t xs = sb + (uint32_t)(nxt & 1) * 2 * TILE_U * 4;
            gemm_issue(X, W, xs, xs + TILE_U * 4, rowBase, colBase, K,
                       nxt << 5, tid);
        }
        asm volatile("cp.async.commit_group;" ::: "memory");
        asm volatile("cp.async.wait_group 1;" ::: "memory");
        __syncthreads();

        const unsigned* Xc = (const unsigned*)smf + (size_t)(ch & 1) * 2 * TILE_U;
        const unsigned* Wc = Xc + TILE_U;

        #pragma unroll
        for (int kb = 0; kb < 32; kb += 8) {
            unsigned a[2][4];
            #pragma unroll
            for (int i = 0; i < 2; i++) {
                int mB = wm * 32 + i * 16;
                const unsigned* x0 = Xc + (mB + g) * S36;
                const unsigned* x1 = Xc + (mB + g + 8) * S36;
                a[i][0] = x0[kb + t];
                a[i][1] = x1[kb + t];
                a[i][2] = x0[kb + t + 4];
                a[i][3] = x1[kb + t + 4];
            }
            #pragma unroll
            for (int j = 0; j < 8; j++) {
                const unsigned* wr = Wc + (wn * 64 + j * 8 + g) * S36;
                unsigned b0 = wr[kb + t];
                unsigned b1 = wr[kb + t + 4];
                #pragma unroll
                for (int i = 0; i < 2; i++) {
                    asm volatile(
                        "mma.sync.aligned.m16n8k8.row.col.f32.tf32.tf32.f32 "
                        "{%0,%1,%2,%3}, {%4,%5,%6,%7}, {%8,%9}, {%0,%1,%2,%3};"
                        : "+f"(acc[i][j][0]), "+f"(acc[i][j][1]),
                          "+f"(acc[i][j][2]), "+f"(acc[i][j][3])
                        : "r"(a[i][0]), "r"(a[i][1]), "r"(a[i][2]), "r"(a[i][3]),
                          "r"(b0), "r"(b1));
                }
            }
        }
        __syncthreads();
    }

    #pragma unroll
    for (int i = 0; i < 2; i++) {
        int r0 = rowBase + wm * 32 + i * 16 + g;
        #pragma unroll
        for (int j = 0; j < 8; j++) {
            int n = colBase + wn * 64 + j * 8 + 2 * t;
            size_t i0 = (size_t)r0 * N + n;
            size_t i1 = (size_t)(r0 + 8) * N + n;
            if (EPI == 0) {
                *(float2*)&Y[i0] = make_float2(acc[i][j][0], acc[i][j][1]);
                *(float2*)&Y[i1] = make_float2(acc[i][j][2], acc[i][j][3]);
            } else if (EPI == 1) {
                float2 y0 = *(float2*)&Y[i0];
                float2 y1 = *(float2*)&Y[i1];
                y0.x += acc[i][j][0]; y0.y += acc[i][j][1];
                y1.x += acc[i][j][2]; y1.y += acc[i][j][3];
                *(float2*)&Y[i0] = y0;
                *(float2*)&Y[i1] = y1;
            } else {
                *(float2*)&Y[i0] = make_float2(roundtf(gelu_exact(acc[i][j][0])),
                                               roundtf(gelu_exact(acc[i][j][1])));
                *(float2*)&Y[i1] = make_float2(roundtf(gelu_exact(acc[i][j][2])),
                                               roundtf(gelu_exact(acc[i][j][3])));
            }
        }
    }
}

// ---------------------------------------------------------------------------
// Flash attention, balanced pairing (R9; epilogue now tf32-rounds its output,
// which feeds the proj GEMM)
// ---------------------------------------------------------------------------
__global__ __launch_bounds__(256)
void fattn_kernel(const float* __restrict__ qkv,
                  float* __restrict__ out) {
    int qp = blockIdx.x;
    int h  = blockIdx.y;
    int b  = blockIdx.z;
    int tid = threadIdx.x;
    int tx = tid & 15;
    int ty = tid >> 4;

    __shared__ float Qs[64][64];
    __shared__ float KPs[64][64];
    __shared__ float Vs[64][64];

    int lq = tid & 63;
    int dg = (tid >> 6) * 16;

    #pragma unroll 1
    for (int ph = 0; ph < 2; ph++) {
        int qt = ph ? (NQT - 1 - qp) : qp;

        {
            const float* qb = qkv + ((size_t)(b * SEQ_T + qt * 64 + lq)) * (3 * D_MODEL)
                            + h * D_HEAD;
            #pragma unroll
            for (int it = 0; it < 4; it++) {
                float4 v = *(const float4*)(qb + dg + it * 4);
                Qs[dg + it * 4 + 0][lq] = v.x;
                Qs[dg + it * 4 + 1][lq] = v.y;
                Qs[dg + it * 4 + 2][lq] = v.z;
                Qs[dg + it * 4 + 3][lq] = v.w;
            }
        }

        float accO[4][4];
        #pragma unroll
        for (int i = 0; i < 4; i++)
            #pragma unroll
            for (int j = 0; j < 4; j++) accO[i][j] = 0.0f;
        float m_i[4] = {-1e30f, -1e30f, -1e30f, -1e30f};
        float l_i[4] = {0.0f, 0.0f, 0.0f, 0.0f};

        __syncthreads();

        for (int kt = 0; kt <= qt; kt++) {
            {
                const float* kb = qkv + ((size_t)(b * SEQ_T + kt * 64 + lq)) * (3 * D_MODEL)
                                + D_MODEL + h * D_HEAD;
                #pragma unroll
                for (int it = 0; it < 4; it++) {
                    float4 v = *(const float4*)(kb + dg + it * 4);
                    KPs[dg + it * 4 + 0][lq] = v.x;
                    KPs[dg + it * 4 + 1][lq] = v.y;
                    KPs[dg + it * 4 + 2][lq] = v.z;
                    KPs[dg + it * 4 + 3][lq] = v.w;
                }
                #pragma unroll
                for (int it = 0; it < 4; it++) {
                    int f = it * 256 + tid;
                    int kk = f >> 4;
                    int d4 = (f & 15) * 4;
                    const float* vb = qkv + ((size_t)(b * SEQ_T + kt * 64 + kk)) * (3 * D_MODEL)
                                    + 2 * D_MODEL + h * D_HEAD + d4;
                    float4 v = *(const float4*)vb;
                    *(float4*)&Vs[kk][d4] = v;
                }
            }
            __syncthreads();

            float s[4][4];
            #pragma unroll
            for (int i = 0; i < 4; i++)
                #pragma unroll
                for (int j = 0; j < 4; j++) s[i][j] = 0.0f;

            #pragma unroll 8
            for (int d = 0; d < 64; d++) {
                float4 qa = *(const float4*)&Qs[d][ty * 4];
                float4 ka = *(const float4*)&KPs[d][tx * 4];
                float a[4] = {qa.x, qa.y, qa.z, qa.w};
                float kv[4] = {ka.x, ka.y, ka.z, ka.w};
                #pragma unroll
                for (int i = 0; i < 4; i++)
                    #pragma unroll
                    for (int j = 0; j < 4; j++)
                        s[i][j] += a[i] * kv[j];
            }

            #pragma unroll
            for (int i = 0; i < 4; i++)
                #pragma unroll
                for (int j = 0; j < 4; j++) {
                    s[i][j] *= 0.125f;
                    if (kt == qt) {
                        int gq = ty * 4 + i;
                        int gk = tx * 4 + j;
                        if (gk > gq) s[i][j] = -1e30f;
                    }
                }

            float p[4][4];
            #pragma unroll
            for (int i = 0; i < 4; i++) {
                float rmax = fmaxf(fmaxf(s[i][0], s[i][1]), fmaxf(s[i][2], s[i][3]));
                #pragma unroll
                for (int off = 1; off < 16; off <<= 1)
                    rmax = fmaxf(rmax, __shfl_xor_sync(0xffffffffu, rmax, off));
                float m_new = fmaxf(m_i[i], rmax);
                float scale = __expf(m_i[i] - m_new);
                float rs = 0.0f;
                #pragma unroll
                for (int j = 0; j < 4; j++) {
                    p[i][j] = __expf(s[i][j] - m_new);
                    rs += p[i][j];
                }
                #pragma unroll
                for (int off = 1; off < 16; off <<= 1)
                    rs += __shfl_xor_sync(0xffffffffu, rs, off);
                l_i[i] = l_i[i] * scale + rs;
                m_i[i] = m_new;
                #pragma unroll
                for (int j = 0; j < 4; j++) accO[i][j] *= scale;
            }

            __syncthreads();

            #pragma unroll
            for (int i = 0; i < 4; i++)
                *(float4*)&KPs[ty * 4 + i][tx * 4] =
                    make_float4(p[i][0], p[i][1], p[i][2], p[i][3]);
            __syncthreads();

            #pragma unroll 4
            for (int k = 0; k < 64; k++) {
                float4 vv = *(const float4*)&Vs[k][tx * 4];
                float v4[4] = {vv.x, vv.y, vv.z, vv.w};
                #pragma unroll
                for (int i = 0; i < 4; i++) {
                    float pk = KPs[ty * 4 + i][k];
                    #pragma unroll
                    for (int j = 0; j < 4; j++)
                        accO[i][j] += pk * v4[j];
                }
            }
            __syncthreads();
        }

        #pragma unroll
        for (int i = 0; i < 4; i++) {
            float inv = 1.0f / l_i[i];
            size_t row = (size_t)(b * SEQ_T + qt * 64 + ty * 4 + i);
            float* orow = out + row * D_MODEL + h * D_HEAD + tx * 4;
            orow[0] = roundtf(accO[i][0] * inv);
            orow[1] = roundtf(accO[i][1] * inv);
            orow[2] = roundtf(accO[i][2] * inv);
            orow[3] = roundtf(accO[i][3] * inv);
        }
    }
}

// ---------------------------------------------------------------------------
// Host launcher
// ---------------------------------------------------------------------------
extern "C" void kernel_launch(void* const* d_in, const int* in_sizes, int n_in,
                              void* d_out, int out_size) {
    const int*   x       = (const int*)  d_in[0];
    const float* tok_emb = (const float*)d_in[1];
    const float* pos_emb = (const float*)d_in[2];
    const float* qkv_w   = (const float*)d_in[3];
    const float* proj_w  = (const float*)d_in[4];
    const float* ln1_w   = (const float*)d_in[5];
    const float* ln1_b   = (const float*)d_in[6];
    const float* ln2_w   = (const float*)d_in[7];
    const float* ln2_b   = (const float*)d_in[8];
    const float* fc1_w   = (const float*)d_in[9];
    const float* fc2_w   = (const float*)d_in[10];
    const float* lnf_w   = (const float*)d_in[11];
    const float* lnf_b   = (const float*)d_in[12];
    const float* head_w  = (const float*)d_in[13];
    float* out = (float*)d_out;

    float *ph, *pln, *pqkv, *pattn, *pff;
    float *pwq, *pwp, *pw1, *pw2, *pwh;
    cudaGetSymbolAddress((void**)&ph,    g_h);
    cudaGetSymbolAddress((void**)&pln,   g_ln);
    cudaGetSymbolAddress((void**)&pqkv,  g_qkv);
    cudaGetSymbolAddress((void**)&pattn, g_attn);
    cudaGetSymbolAddress((void**)&pff,   g_ff);
    cudaGetSymbolAddress((void**)&pwq,   g_wqkv);
    cudaGetSymbolAddress((void**)&pwp,   g_wproj);
    cudaGetSymbolAddress((void**)&pw1,   g_wfc1);
    cudaGetSymbolAddress((void**)&pw2,   g_wfc2);
    cudaGetSymbolAddress((void**)&pwh,   g_whead);

    cudaFuncSetAttribute(gemm_tf32_kernel<0>,
                         cudaFuncAttributeMaxDynamicSharedMemorySize, GEMM_SMEM);
    cudaFuncSetAttribute(gemm_tf32_kernel<1>,
                         cudaFuncAttributeMaxDynamicSharedMemorySize, GEMM_SMEM);
    cudaFuncSetAttribute(gemm_tf32_kernel<2>,
                         cudaFuncAttributeMaxDynamicSharedMemorySize, GEMM_SMEM);

    // weight pre-rounding (tf32 RNA), once per call
    {
        int n;
        n = DEPTH * 3 * D_MODEL * D_MODEL;
        round_tf32_kernel<<<(n + 255) / 256, 256>>>(qkv_w, pwq, n);
        n = DEPTH * D_MODEL * D_MODEL;
        round_tf32_kernel<<<(n + 255) / 256, 256>>>(proj_w, pwp, n);
        n = DEPTH * D_FF * D_MODEL;
        round_tf32_kernel<<<(n + 255) / 256, 256>>>(fc1_w, pw1, n);
        n = DEPTH * D_MODEL * D_FF;
        round_tf32_kernel<<<(n + 255) / 256, 256>>>(fc2_w, pw2, n);
        n = VOCAB * D_MODEL;
        round_tf32_kernel<<<(n + 255) / 256, 256>>>(head_w, pwh, n);
    }

    embed_kernel<<<(MROWS * D_MODEL + 255) / 256, 256>>>(x, tok_emb, pos_emb, ph);

    for (int l = 0; l < DEPTH; l++) {
        const float* qw  = pwq + (size_t)l * 3 * D_MODEL * D_MODEL;
        const float* pw  = pwp + (size_t)l * D_MODEL * D_MODEL;
        const float* f1w = pw1 + (size_t)l * D_FF * D_MODEL;
        const float* f2w = pw2 + (size_t)l * D_MODEL * D_FF;

        ln_kernel<<<MROWS, 256>>>(ph, ln1_w + l * D_MODEL, ln1_b + l * D_MODEL, pln);

        gemm_tf32_kernel<0><<<dim3(3 * D_MODEL / 128, MROWS / 128), 256, GEMM_SMEM>>>(
            pln, qw, pqkv, MROWS, 3 * D_MODEL, D_MODEL);

        fattn_kernel<<<dim3(NQT / 2, N_HEADS, BB), 256>>>(pqkv, pattn);

        gemm_tf32_kernel<1><<<dim3(D_MODEL / 128, MROWS / 128), 256, GEMM_SMEM>>>(
            pattn, pw, ph, MROWS, D_MODEL, D_MODEL);

        ln_kernel<<<MROWS, 256>>>(ph, ln2_w + l * D_MODEL, ln2_b + l * D_MODEL, pln);

        gemm_tf32_kernel<2><<<dim3(D_FF / 128, MROWS / 128), 256, GEMM_SMEM>>>(
            pln, f1w, pff, MROWS, D_FF, D_MODEL);

        gemm_tf32_kernel<1><<<dim3(D_MODEL / 128, MROWS / 128), 256, GEMM_SMEM>>>(
            pff, f2w, ph, MROWS, D_MODEL, D_FF);
    }

    ln_kernel<<<MROWS, 256>>>(ph, lnf_w, lnf_b, pln);
    gemm_tf32_kernel<0><<<dim3(VOCAB / 128, MROWS / 128), 256, GEMM_SMEM>>>(
        pln, pwh, out, MROWS, VOCAB, D_MODEL);

    (void)in_sizes; (void)n_in; (void)out_size;
}